// round 7
// baseline (speedup 1.0000x reference)
#include <cuda_runtime.h>
#include <math.h>

// Problem constants (GCN_17411797418393): N=40000 nodes, E=640000 edges, D=125.
#define NN 40000
#define EE 640000
#define DD 125
#define DP 128   // padded feature dim for float4 access

// ---------------- scratch (static device globals; no allocs) ----------------
__device__ __align__(16) float g_h[(size_t)NN * DP];   // GEMM output / agg input
__device__ __align__(16) float g_a[(size_t)NN * DP];   // agg output / GEMM input
__device__ int   g_deg[NN];
__device__ float g_dinv[NN];
__device__ int   g_rowstart[NN + 1];
__device__ int   g_cursor[NN];
__device__ int   g_csr_src[EE];
__device__ float g_csr_w[EE];
__device__ int   g_src[EE];
__device__ int   g_dst[EE];
__device__ unsigned g_odd_or;

// ---------------- edge_index dtype detection + decode ----------------
// edge_index is logically int64 [2,E] in the reference, but JAX default config
// demotes int64 -> int32. Detect on device: if the buffer is int64 (values
// < 2^31, little-endian), every odd 32-bit word among the first 2E words is 0.
// Also initializes g_deg (self loop = 1) to save a launch.
__global__ void k_init(int n) {
    int i = blockIdx.x * blockDim.x + threadIdx.x;
    if (i == 0) g_odd_or = 0u;
    if (i < n) g_deg[i] = 1;
}

__global__ void k_detect(const unsigned* __restrict__ w, int E) {
    // probe words [0, 2E): safe for both dtypes (int32 buffer has exactly 2E words)
    unsigned v = 0;
    for (int i = blockIdx.x * blockDim.x + threadIdx.x; i < E;
         i += gridDim.x * blockDim.x)
        v |= w[2 * i + 1];
    #pragma unroll
    for (int off = 16; off > 0; off >>= 1)
        v |= __shfl_xor_sync(0xFFFFFFFFu, v, off);
    if ((threadIdx.x & 31) == 0 && v) atomicOr(&g_odd_or, v);
}

// Decode into int32 src/dst arrays and count in-degrees in one pass.
__global__ void k_decode_count(const unsigned* __restrict__ w, int E) {
    int e = blockIdx.x * blockDim.x + threadIdx.x;
    if (e >= E) return;
    int s, d;
    if (g_odd_or == 0u) {           // int64 layout: 4E words, src at 2e, dst at 2E+2e
        s = (int)w[2 * e];
        d = (int)w[2 * E + 2 * e];
    } else {                        // int32 layout: 2E words
        s = (int)w[e];
        d = (int)w[E + e];
    }
    g_src[e] = s;
    g_dst[e] = d;
    atomicAdd(&g_deg[d], 1);
}

__global__ void k_dinv(int n) {
    int i = blockIdx.x * blockDim.x + threadIdx.x;
    if (i < n) g_dinv[i] = rsqrtf((float)g_deg[i]);
}

// Single-block exclusive scan of (deg[i]-1) -> rowstart / cursor.
__global__ void k_scan(int n) {
    __shared__ int sm[1024];
    __shared__ int carry_s;
    int tid = threadIdx.x;
    if (tid == 0) carry_s = 0;
    __syncthreads();
    for (int base = 0; base < n; base += 8192) {
        int v[8];
        int s = 0;
        #pragma unroll
        for (int u = 0; u < 8; u++) {
            int i = base + tid * 8 + u;
            v[u] = (i < n) ? (g_deg[i] - 1) : 0;
            s += v[u];
        }
        sm[tid] = s;
        __syncthreads();
        for (int off = 1; off < 1024; off <<= 1) {
            int t = (tid >= off) ? sm[tid - off] : 0;
            __syncthreads();
            sm[tid] += t;
            __syncthreads();
        }
        int excl = sm[tid] - s + carry_s;
        int total = sm[1023];
        __syncthreads();
        int run = excl;
        #pragma unroll
        for (int u = 0; u < 8; u++) {
            int i = base + tid * 8 + u;
            if (i < n) { g_rowstart[i] = run; g_cursor[i] = run; }
            run += v[u];
        }
        if (tid == 0) carry_s += total;
        __syncthreads();
    }
    if (tid == 0) g_rowstart[n] = carry_s;
}

__global__ void k_scatter(int E) {
    int e = blockIdx.x * blockDim.x + threadIdx.x;
    if (e >= E) return;
    int s = g_src[e];
    int d = g_dst[e];
    int pos = atomicAdd(&g_cursor[d], 1);
    g_csr_src[pos] = s;
    g_csr_w[pos]   = g_dinv[s] * g_dinv[d];
}

// ---------------- GEMM: out[N,128pad] = X[N,si] @ W[125,125] (pad cols = 0) ---
// 256 threads; block covers 32 rows. warp = row-group (4 rows), lane = col-group.
// 4x4 register tile: per kk, 2 x LDS.128 feed 16 FMAs -> FMA-pipe bound.
__global__ void __launch_bounds__(256, 4)
k_gemm(const float* __restrict__ X, const float* __restrict__ W,
       float* __restrict__ out, int n, int si) {
    __shared__ __align__(16) float xs[125 * 36];  // xs[k*36 + r], padded stride
    __shared__ __align__(16) float ws[25 * 128];  // one K-tile of W, col-padded
    int tid  = threadIdx.x;
    int lane = tid & 31;    // col group: cols lane*4 .. +3
    int warp = tid >> 5;    // row group: rows warp*4 .. +3
    int row0 = blockIdx.x * 32;

    for (int idx = tid; idx < 32 * 125; idx += 256) {
        int r = idx / 125;
        int k = idx - r * 125;
        int row = min(row0 + r, n - 1);   // clamp (no-op when 32 | n)
        xs[k * 36 + r] = X[(size_t)row * si + k];
    }

    float acc[4][4];
    #pragma unroll
    for (int r = 0; r < 4; r++)
        #pragma unroll
        for (int c = 0; c < 4; c++) acc[r][c] = 0.f;

    for (int kt = 0; kt < 5; kt++) {
        __syncthreads();
        for (int idx = tid; idx < 25 * 128; idx += 256) {
            int j = idx & 127;
            int k = idx >> 7;
            ws[idx] = (j < DD) ? W[(size_t)(kt * 25 + k) * DD + j] : 0.f;
        }
        __syncthreads();
        #pragma unroll
        for (int kk = 0; kk < 25; kk++) {
            float4 w4 = *(const float4*)&ws[kk * 128 + lane * 4];
            float4 x4 = *(const float4*)&xs[(kt * 25 + kk) * 36 + warp * 4];
            acc[0][0] += x4.x * w4.x; acc[0][1] += x4.x * w4.y; acc[0][2] += x4.x * w4.z; acc[0][3] += x4.x * w4.w;
            acc[1][0] += x4.y * w4.x; acc[1][1] += x4.y * w4.y; acc[1][2] += x4.y * w4.z; acc[1][3] += x4.y * w4.w;
            acc[2][0] += x4.z * w4.x; acc[2][1] += x4.z * w4.y; acc[2][2] += x4.z * w4.z; acc[2][3] += x4.z * w4.w;
            acc[3][0] += x4.w * w4.x; acc[3][1] += x4.w * w4.y; acc[3][2] += x4.w * w4.z; acc[3][3] += x4.w * w4.w;
        }
    }
    #pragma unroll
    for (int r = 0; r < 4; r++) {
        int row = row0 + warp * 4 + r;
        if (row < n) {
            float4 o = make_float4(acc[r][0], acc[r][1], acc[r][2], acc[r][3]);
            *(float4*)&out[(size_t)row * DP + lane * 4] = o;
        }
    }
}

// ---------------- aggregation (warp per node), CSR, atomics-free -------------
// MODE 0: out = relu(selfloop + sum + bias) -> padded buffer
// MODE 1: log_softmax(selfloop + sum + bias) -> final_out [N,125]
// Edge loop unrolled x2 with independent accumulators for MLP=2 gathers.
template <int MODE>
__global__ void __launch_bounds__(256)
k_agg(const float* __restrict__ h, const float* __restrict__ bias,
      float* __restrict__ out, float* __restrict__ final_out, int n) {
    int gwarp = (blockIdx.x * blockDim.x + threadIdx.x) >> 5;
    int lane  = threadIdx.x & 31;
    if (gwarp >= n) return;
    int node = gwarp;
    const float4* h4 = (const float4*)h;

    float di = g_dinv[node];
    float w0 = di * di;
    float4 acc = h4[(size_t)node * 32 + lane];
    acc.x *= w0; acc.y *= w0; acc.z *= w0; acc.w *= w0;
    float4 acc2 = make_float4(0.f, 0.f, 0.f, 0.f);

    int e  = g_rowstart[node];
    int e1 = g_rowstart[node + 1];
    for (; e + 1 < e1; e += 2) {
        int   s0 = __ldg(&g_csr_src[e]);
        int   s1 = __ldg(&g_csr_src[e + 1]);
        float wa = __ldg(&g_csr_w[e]);
        float wb = __ldg(&g_csr_w[e + 1]);
        float4 v0 = h4[(size_t)s0 * 32 + lane];
        float4 v1 = h4[(size_t)s1 * 32 + lane];
        acc.x  += v0.x * wa; acc.y  += v0.y * wa; acc.z  += v0.z * wa; acc.w  += v0.w * wa;
        acc2.x += v1.x * wb; acc2.y += v1.y * wb; acc2.z += v1.z * wb; acc2.w += v1.w * wb;
    }
    if (e < e1) {
        int   s = __ldg(&g_csr_src[e]);
        float w = __ldg(&g_csr_w[e]);
        float4 v = h4[(size_t)s * 32 + lane];
        acc.x += v.x * w; acc.y += v.y * w; acc.z += v.z * w; acc.w += v.w * w;
    }
    acc.x += acc2.x; acc.y += acc2.y; acc.z += acc2.z; acc.w += acc2.w;

    int j0 = lane * 4;
    acc.x += (j0 + 0 < DD) ? bias[j0 + 0] : 0.f;
    acc.y += (j0 + 1 < DD) ? bias[j0 + 1] : 0.f;
    acc.z += (j0 + 2 < DD) ? bias[j0 + 2] : 0.f;
    acc.w += (j0 + 3 < DD) ? bias[j0 + 3] : 0.f;

    if (MODE == 0) {
        acc.x = fmaxf(acc.x, 0.f); acc.y = fmaxf(acc.y, 0.f);
        acc.z = fmaxf(acc.z, 0.f); acc.w = fmaxf(acc.w, 0.f);
        ((float4*)out)[(size_t)node * 32 + lane] = acc;
    } else {
        float vx = (j0 + 0 < DD) ? acc.x : -1e30f;
        float vy = (j0 + 1 < DD) ? acc.y : -1e30f;
        float vz = (j0 + 2 < DD) ? acc.z : -1e30f;
        float vw = (j0 + 3 < DD) ? acc.w : -1e30f;
        float m = fmaxf(fmaxf(vx, vy), fmaxf(vz, vw));
        #pragma unroll
        for (int off = 16; off > 0; off >>= 1)
            m = fmaxf(m, __shfl_xor_sync(0xFFFFFFFFu, m, off));
        float ssum = expf(vx - m) + expf(vy - m) + expf(vz - m) + expf(vw - m);
        #pragma unroll
        for (int off = 16; off > 0; off >>= 1)
            ssum += __shfl_xor_sync(0xFFFFFFFFu, ssum, off);
        float lse = m + logf(ssum);
        float* o = final_out + (size_t)node * DD;
        if (j0 + 0 < DD) o[j0 + 0] = vx - lse;
        if (j0 + 1 < DD) o[j0 + 1] = vy - lse;
        if (j0 + 2 < DD) o[j0 + 2] = vz - lse;
        if (j0 + 3 < DD) o[j0 + 3] = vw - lse;
    }
}

// ---------------- launch --------------------------------------------------
extern "C" void kernel_launch(void* const* d_in, const int* in_sizes, int n_in,
                              void* d_out, int out_size) {
    const float*    x   = (const float*)d_in[0];
    const unsigned* eiw = (const unsigned*)d_in[1];   // raw words; dtype sniffed on device
    const float*    W1  = (const float*)d_in[2];
    const float*    b1  = (const float*)d_in[3];
    const float*    W2  = (const float*)d_in[4];
    const float*    b2  = (const float*)d_in[5];
    float*          out = (float*)d_out;

    const int N = in_sizes[0] / DD;   // 40000
    const int E = in_sizes[1] / 2;    // 640000

    float *hbuf, *abuf;
    cudaGetSymbolAddress((void**)&hbuf, g_h);
    cudaGetSymbolAddress((void**)&abuf, g_a);

    const int T = 512;
    // decode edge_index (handles int32 or int64 storage) + degree count
    k_init<<<(N + T - 1) / T, T>>>(N);
    k_detect<<<128, T>>>(eiw, E);
    k_decode_count<<<(E + T - 1) / T, T>>>(eiw, E);

    // graph structure (built once per launch, reused by both layers)
    k_dinv<<<(N + T - 1) / T, T>>>(N);
    k_scan<<<1, 1024>>>(N);
    k_scatter<<<(E + T - 1) / T, T>>>(E);

    int gemm_blocks = (N + 31) / 32;
    int agg_blocks  = (N * 32 + 255) / 256;  // warp per node

    // layer 1: h = x @ W1 ; a = relu(aggregate(h) + b1)
    k_gemm<<<gemm_blocks, 256>>>(x, W1, hbuf, N, DD);
    k_agg<0><<<agg_blocks, 256>>>(hbuf, b1, abuf, nullptr, N);

    // layer 2: h = a @ W2 ; out = log_softmax(aggregate(h) + b2)
    k_gemm<<<gemm_blocks, 256>>>(abuf, W2, hbuf, N, DP);
    k_agg<1><<<agg_blocks, 256>>>(hbuf, b2, nullptr, out, N);
}